// round 12
// baseline (speedup 1.0000x reference)
#include <cuda_runtime.h>
#include <cuda_fp16.h>
#include <cuda_bf16.h>

#define N_NODES 50000
#define F_IN    16
#define N_HID   32
#define N_EDGES 1000000
#define EDGE_S  8
#define SROWS   9
#define BN_EPS  1e-3f
#define MSCALE  32.0f
#define MINV    0.03125f
#define NTILES  (N_NODES / 16)     // 3125 exactly
// M layout per node: 384 B (3 aligned 128B lines), bytes PERMUTED in o:
//   byte j of s-row (32B at s*32) holds channel o = pi(j) = (j>>1) + (j&1)*16.
// M stores 32*M; g_agg carries 32x values (perm cols); k_node folds /32 into BN.

__device__ uint4 g_M4[N_NODES * 24];       // 19.2 MB fp8 table
__device__ float g_agg[N_NODES * N_HID];   // 6.4 MB, perm cols, 32x scaled
__device__ float g_pooled[N_HID];          // permuted order
__device__ unsigned int g_done;

__device__ __forceinline__ void mma_bf16(float d[4], const unsigned int a[4],
                                         unsigned int b0, unsigned int b1) {
    asm volatile(
        "mma.sync.aligned.m16n8k16.row.col.f32.bf16.bf16.f32 "
        "{%0,%1,%2,%3}, {%4,%5,%6,%7}, {%8,%9}, {%0,%1,%2,%3};"
        : "+f"(d[0]), "+f"(d[1]), "+f"(d[2]), "+f"(d[3])
        : "r"(a[0]), "r"(a[1]), "r"(a[2]), "r"(a[3]), "r"(b0), "r"(b1));
}
__device__ __forceinline__ unsigned int cvt2e4(float hi, float lo) {
    unsigned short p;
    asm("cvt.rn.satfinite.e4m3x2.f32 %0, %1, %2;" : "=h"(p) : "f"(hi), "f"(lo));
    return (unsigned int)p;
}
__device__ __forceinline__ unsigned int bf2(float lo, float hi) {
    __nv_bfloat162 h = __floats2bfloat162_rn(lo, hi);
    return *reinterpret_cast<unsigned int*>(&h);
}

// ---------------------------------------------------------------------------
// Tensor-core precompute, smem-staged M writes.
// Block = 4 warps; warp = one 16-node tile. 10 N-groups x 4 n-tiles x
// mma.m16n8k16. M fragments scatter into a 400B-stride smem tile (conflict-
// free), then stream out as 16 coalesced STG.128 rows. Seed stays STG.128.
// Table layout identical to previous rounds -> k_edge unchanged.
// ---------------------------------------------------------------------------
#define PCW   4                        // warps per block
#define NSTRW 100                      // staging words per node (384B + 16B pad)

__global__ void __launch_bounds__(128) k_precompute(const float* __restrict__ x,
                                                    const float* __restrict__ Wk,
                                                    const float* __restrict__ bk,
                                                    const float* __restrict__ Wr,
                                                    const float* __restrict__ bc) {
    __shared__ uint2  Bf[10 * 4 * 32];             // 10 KB  [sg][nt][lane]
    __shared__ float4 bcp4[8];                     // bc permuted, x32
    __shared__ unsigned int stage[PCW * 16 * NSTRW];  // 25.6 KB
    int tid = threadIdx.x;

    for (int idx = tid; idx < 10 * 4 * 32; idx += 128) {
        int l = idx & 31, nt = (idx >> 5) & 3, sg = idx >> 7;
        int t = l & 3, gid = l >> 2;
        int col = nt * 8 + gid;
        const float* Ws = (sg < 8) ? (Wk + sg * F_IN * N_HID)
                                   : ((sg == 8) ? bk : Wr);
        float v0 = Ws[(2*t)   * N_HID + col], v1 = Ws[(2*t+1) * N_HID + col];
        float v2 = Ws[(2*t+8) * N_HID + col], v3 = Ws[(2*t+9) * N_HID + col];
        Bf[idx] = make_uint2(bf2(v0 * MSCALE, v1 * MSCALE),
                             bf2(v2 * MSCALE, v3 * MSCALE));
    }
    if (tid < N_HID) {
        int o = (tid >> 1) + ((tid & 1) << 4);        // pi(tid)
        reinterpret_cast<float*>(bcp4)[tid] = bc[o] * MSCALE;
    }
    if (blockIdx.x == 0) {
        if (tid < N_HID) g_pooled[tid] = 0.f;
        if (tid == 32)   g_done = 0;
    }
    __syncthreads();

    int wid = tid >> 5, lane = tid & 31;
    int tile = blockIdx.x * PCW + wid;
    if (tile >= NTILES) return;
    int nb = tile * 16;
    int t = lane & 3, gr = lane >> 2;
    unsigned int* st = stage + wid * (16 * NSTRW);

    // A fragment: rows {gr, gr+8}, k-cols {2t,2t+1} and {2t+8,2t+9}
    const float2* xr0 = reinterpret_cast<const float2*>(x) + (nb + gr) * 8;
    const float2* xr1 = reinterpret_cast<const float2*>(x) + (nb + gr + 8) * 8;
    unsigned int a[4];
    { float2 v;
      v = xr0[t];     a[0] = bf2(v.x, v.y);
      v = xr1[t];     a[1] = bf2(v.x, v.y);
      v = xr0[t + 4]; a[2] = bf2(v.x, v.y);
      v = xr1[t + 4]; a[3] = bf2(v.x, v.y);
    }

#pragma unroll
    for (int sg = 0; sg < 9; sg++) {
        float d[4][4];
#pragma unroll
        for (int nt = 0; nt < 4; nt++) {
            d[nt][0] = d[nt][1] = d[nt][2] = d[nt][3] = 0.f;
            uint2 b = Bf[sg * 128 + nt * 32 + lane];
            mma_bf16(d[nt], a, b.x, b.y);
        }
        unsigned int w00 = (cvt2e4(d[2][1], d[0][1]) << 16) | cvt2e4(d[2][0], d[0][0]);
        unsigned int w01 = (cvt2e4(d[3][1], d[1][1]) << 16) | cvt2e4(d[3][0], d[1][0]);
        unsigned int w10 = (cvt2e4(d[2][3], d[0][3]) << 16) | cvt2e4(d[2][2], d[0][2]);
        unsigned int w11 = (cvt2e4(d[3][3], d[1][3]) << 16) | cvt2e4(d[3][2], d[1][2]);
        int base0 = gr * NSTRW + sg * 8 + t;          // node gr
        int base1 = (gr + 8) * NSTRW + sg * 8 + t;    // node gr+8
        st[base0]     = w00;
        st[base0 + 4] = w01;
        st[base1]     = w10;
        st[base1 + 4] = w11;
    }
    // seed group (Wr): fp32 out + bc, permuted cols, 32x scaled (coalesced)
    {
        float d[4][4];
#pragma unroll
        for (int nt = 0; nt < 4; nt++) {
            d[nt][0] = d[nt][1] = d[nt][2] = d[nt][3] = 0.f;
            uint2 b = Bf[9 * 128 + nt * 32 + lane];
            mma_bf16(d[nt], a, b.x, b.y);
        }
        float4 bl = bcp4[t], bh = bcp4[4 + t];
        float4* ag = reinterpret_cast<float4*>(g_agg);
        ag[(nb + gr) * 8 + t]         = make_float4(d[0][0] + bl.x, d[2][0] + bl.y, d[0][1] + bl.z, d[2][1] + bl.w);
        ag[(nb + gr) * 8 + 4 + t]     = make_float4(d[1][0] + bh.x, d[3][0] + bh.y, d[1][1] + bh.z, d[3][1] + bh.w);
        ag[(nb + gr + 8) * 8 + t]     = make_float4(d[0][2] + bl.x, d[2][2] + bl.y, d[0][3] + bl.z, d[2][3] + bl.w);
        ag[(nb + gr + 8) * 8 + 4 + t] = make_float4(d[1][2] + bh.x, d[3][2] + bh.y, d[1][3] + bh.z, d[3][3] + bh.w);
    }

    // stream the staged M tile out coalesced: 16 rows x 384B (24 uint4)
    __syncwarp();
    if (lane < 24) {
#pragma unroll 8
        for (int n = 0; n < 16; n++) {
            uint4 v = *reinterpret_cast<const uint4*>(&st[n * NSTRW + 4 * lane]);
            g_M4[(nb + n) * 24 + lane] = v;
        }
    }
}

// ---------------------------------------------------------------------------
// Per-edge gather + scatter (UNCHANGED). 8 lanes/edge, 2x LDG.128 + 1x LDG.32,
// reduce-scatter butterfly, red.global.add.v4.f32. At LTS throughput cap.
// ---------------------------------------------------------------------------
__device__ __forceinline__ __half2 cvt8(unsigned int v) {
    unsigned int h;
    asm("cvt.rn.f16x2.e4m3x2 %0, %1;" : "=r"(h) : "h"((unsigned short)v));
    return *reinterpret_cast<__half2*>(&h);
}
__device__ __forceinline__ __half2 shx(__half2 v, int m) {
    unsigned int u = *reinterpret_cast<unsigned int*>(&v);
    u = __shfl_xor_sync(0xffffffffu, u, m);
    return *reinterpret_cast<__half2*>(&u);
}

__global__ void __launch_bounds__(256) k_edge(const int* __restrict__ ei,
                                              const float* __restrict__ e) {
    int gtid = blockIdx.x * 256 + threadIdx.x;
    int edge = gtid >> 3;
    if (edge >= N_EDGES) return;
    int g    = threadIdx.x & 7;
    int hidx = g >> 1;
    bool oddh = hidx & 1;
    bool odd2 = (hidx & 2) != 0;

    int2 pe = reinterpret_cast<const int2*>(ei)[edge];
    int src = pe.x, tgt = pe.y;

    __half2 eA = __float2half2_rn(e[edge * EDGE_S + hidx]);
    __half2 eB = __float2half2_rn(e[edge * EDGE_S + 4 + hidx]);

    const uint4* nb = g_M4 + src * 24;
    uint4 q0 = nb[g];
    uint4 q1 = nb[8 + g];

    __half2 r0 = __hmul2(eA, cvt8(q0.x)), r1 = __hmul2(eA, cvt8(q0.x >> 16));
    __half2 r2 = __hmul2(eA, cvt8(q0.y)), r3 = __hmul2(eA, cvt8(q0.y >> 16));
    __half2 r4 = __hmul2(eA, cvt8(q0.z)), r5 = __hmul2(eA, cvt8(q0.z >> 16));
    __half2 r6 = __hmul2(eA, cvt8(q0.w)), r7 = __hmul2(eA, cvt8(q0.w >> 16));
    r0 = __hfma2(eB, cvt8(q1.x), r0); r1 = __hfma2(eB, cvt8(q1.x >> 16), r1);
    r2 = __hfma2(eB, cvt8(q1.y), r2); r3 = __hfma2(eB, cvt8(q1.y >> 16), r3);
    r4 = __hfma2(eB, cvt8(q1.z), r4); r5 = __hfma2(eB, cvt8(q1.z >> 16), r5);
    r6 = __hfma2(eB, cvt8(q1.w), r6); r7 = __hfma2(eB, cvt8(q1.w >> 16), r7);

    __half2 k0 = __hadd2(oddh ? r2 : r0, shx(oddh ? r0 : r2, 2));
    __half2 k1 = __hadd2(oddh ? r3 : r1, shx(oddh ? r1 : r3, 2));
    __half2 k2 = __hadd2(oddh ? r6 : r4, shx(oddh ? r4 : r6, 2));
    __half2 k3 = __hadd2(oddh ? r7 : r5, shx(oddh ? r5 : r7, 2));
    __half2 c0 = __hadd2(odd2 ? k2 : k0, shx(odd2 ? k0 : k2, 4));
    __half2 c1 = __hadd2(odd2 ? k3 : k1, shx(odd2 ? k1 : k3, 4));

    int ochunk = 16 * (g & 1) + 4 * hidx;
    unsigned int m8 = *reinterpret_cast<const unsigned int*>(
        reinterpret_cast<const char*>(nb) + 256 + ochunk);
    c0 = __hadd2(c0, cvt8(m8));
    c1 = __hadd2(c1, cvt8(m8 >> 16));

    float2 f0 = __half22float2(c0);
    float2 f1 = __half22float2(c1);

    float* dst = &g_agg[tgt * N_HID + ochunk];
    asm volatile("red.global.add.v4.f32 [%0], {%1, %2, %3, %4};"
                 :: "l"(dst), "f"(f0.x), "f"(f0.y), "f"(f1.x), "f"(f1.y) : "memory");
}

// ---------------------------------------------------------------------------
// h = BN(relu(agg/32)); pool; last block: out = pooled@Wd + bd.
// float4 path: warp = 4 nodes/iter (LDG.128), xor-shuffle pool reduce.
// ---------------------------------------------------------------------------
__global__ void __launch_bounds__(256) k_node(const float* __restrict__ gamma,
                                              const float* __restrict__ beta,
                                              const float* __restrict__ mm,
                                              const float* __restrict__ mv,
                                              const float* __restrict__ Wd,
                                              const float* __restrict__ bd,
                                              float* __restrict__ out) {
    __shared__ float4 scl4[8], shf4[8];
    __shared__ float blk[N_HID];
    __shared__ int last;
    int tid = threadIdx.x;
    if (tid < N_HID) {
        blk[tid] = 0.f;
        int o = (tid >> 1) + ((tid & 1) << 4);        // pi(tid)
        float rs = rsqrtf(mv[o] + BN_EPS) * gamma[o];
        reinterpret_cast<float*>(scl4)[tid] = rs * MINV;
        reinterpret_cast<float*>(shf4)[tid] = beta[o] - mm[o] * rs;
    }
    __syncthreads();

    int lane = tid & 31, w = tid >> 5;
    int q = lane & 7, nsub = lane >> 3;
    float4 sc = scl4[q], sh = shf4[q];
    float4 pool = make_float4(0.f, 0.f, 0.f, 0.f);

    const float4* ag4 = reinterpret_cast<const float4*>(g_agg);
    for (int base = blockIdx.x * 32; base < N_NODES; base += gridDim.x * 32) {
        int node = base + w * 4 + nsub;
        if (node < N_NODES) {
            float4 v = ag4[node * 8 + q];
            pool.x += fmaxf(v.x, 0.f) * sc.x + sh.x;
            pool.y += fmaxf(v.y, 0.f) * sc.y + sh.y;
            pool.z += fmaxf(v.z, 0.f) * sc.z + sh.z;
            pool.w += fmaxf(v.w, 0.f) * sc.w + sh.w;
        }
    }
#pragma unroll
    for (int m = 8; m <= 16; m <<= 1) {
        pool.x += __shfl_xor_sync(0xffffffffu, pool.x, m);
        pool.y += __shfl_xor_sync(0xffffffffu, pool.y, m);
        pool.z += __shfl_xor_sync(0xffffffffu, pool.z, m);
        pool.w += __shfl_xor_sync(0xffffffffu, pool.w, m);
    }
    if (lane < 8) {
        atomicAdd(&blk[4 * lane + 0], pool.x);
        atomicAdd(&blk[4 * lane + 1], pool.y);
        atomicAdd(&blk[4 * lane + 2], pool.z);
        atomicAdd(&blk[4 * lane + 3], pool.w);
    }
    __syncthreads();
    if (tid < N_HID) atomicAdd(&g_pooled[tid], blk[tid]);
    __threadfence();
    if (tid == 0)
        last = (atomicAdd(&g_done, 1u) == gridDim.x - 1) ? 1 : 0;
    __syncthreads();
    if (last) {
        if (tid < N_HID) blk[tid] = atomicAdd(&g_pooled[tid], 0.f);
        __syncthreads();
        if (tid < 3) {
            float acc = bd[tid];
#pragma unroll
            for (int j = 0; j < N_HID; j++) {
                int oj = (j >> 1) + ((j & 1) << 4);
                acc += blk[j] * Wd[oj * 3 + tid];
            }
            out[tid] = acc;
        }
    }
}

// ---------------------------------------------------------------------------
extern "C" void kernel_launch(void* const* d_in, const int* in_sizes, int n_in,
                              void* d_out, int out_size) {
    const float* x   = (const float*)d_in[0];
    const int*   ei  = (const int*)  d_in[1];
    const float* e   = (const float*)d_in[2];
    const float* Wk  = (const float*)d_in[3];
    const float* bk  = (const float*)d_in[4];
    const float* Wr  = (const float*)d_in[5];
    const float* bc  = (const float*)d_in[6];
    const float* ga  = (const float*)d_in[7];
    const float* be  = (const float*)d_in[8];
    const float* mm  = (const float*)d_in[9];
    const float* mv  = (const float*)d_in[10];
    const float* Wd  = (const float*)d_in[11];
    const float* bd  = (const float*)d_in[12];
    float* out = (float*)d_out;

    k_precompute<<<(NTILES + PCW - 1) / PCW, 128>>>(x, Wk, bk, Wr, bc);
    k_edge<<<(N_EDGES * 8 + 255) / 256, 256>>>(ei, e);
    k_node<<<592, 256>>>(ga, be, mm, mv, Wd, bd, out);
}

// round 13
// speedup vs baseline: 1.0017x; 1.0017x over previous
#include <cuda_runtime.h>
#include <cuda_fp16.h>
#include <cuda_bf16.h>

#define N_NODES 50000
#define F_IN    16
#define N_HID   32
#define N_EDGES 1000000
#define EDGE_S  8
#define SROWS   9
#define BN_EPS  1e-3f
#define MSCALE  32.0f
#define MINV    0.03125f
#define NTILES  (N_NODES / 16)     // 3125 exactly
// M layout per node: 384 B (3 aligned 128B lines), bytes PERMUTED in o:
//   byte j of s-row (32B at s*32) holds channel o = pi(j) = (j>>1) + (j&1)*16.
// M stores 32*M; g_agg carries 32x values (perm cols); k_node folds /32 into BN.

__device__ uint4 g_M4[N_NODES * 24];       // 19.2 MB fp8 table
__device__ float g_agg[N_NODES * N_HID];   // 6.4 MB, perm cols, 32x scaled
__device__ float g_pooled[N_HID];          // permuted order
__device__ unsigned int g_done;

__device__ __forceinline__ void mma_bf16(float d[4], const unsigned int a[4],
                                         unsigned int b0, unsigned int b1) {
    asm volatile(
        "mma.sync.aligned.m16n8k16.row.col.f32.bf16.bf16.f32 "
        "{%0,%1,%2,%3}, {%4,%5,%6,%7}, {%8,%9}, {%0,%1,%2,%3};"
        : "+f"(d[0]), "+f"(d[1]), "+f"(d[2]), "+f"(d[3])
        : "r"(a[0]), "r"(a[1]), "r"(a[2]), "r"(a[3]), "r"(b0), "r"(b1));
}
__device__ __forceinline__ unsigned int cvt2e4(float hi, float lo) {
    unsigned short p;
    asm("cvt.rn.satfinite.e4m3x2.f32 %0, %1, %2;" : "=h"(p) : "f"(hi), "f"(lo));
    return (unsigned int)p;
}
__device__ __forceinline__ unsigned int bf2(float lo, float hi) {
    __nv_bfloat162 h = __floats2bfloat162_rn(lo, hi);
    return *reinterpret_cast<unsigned int*>(&h);
}

// ---------------------------------------------------------------------------
// Tensor-core precompute, smem-staged M writes.
// Block = 4 warps; warp = one 16-node tile. 10 N-groups x 4 n-tiles x
// mma.m16n8k16. M fragments scatter into a 400B-stride smem tile (conflict-
// free), then stream out as 16 coalesced STG.128 rows. Seed stays STG.128.
// Table layout identical to previous rounds -> k_edge unchanged.
// ---------------------------------------------------------------------------
#define PCW   4                        // warps per block
#define NSTRW 100                      // staging words per node (384B + 16B pad)

__global__ void __launch_bounds__(128) k_precompute(const float* __restrict__ x,
                                                    const float* __restrict__ Wk,
                                                    const float* __restrict__ bk,
                                                    const float* __restrict__ Wr,
                                                    const float* __restrict__ bc) {
    __shared__ uint2  Bf[10 * 4 * 32];             // 10 KB  [sg][nt][lane]
    __shared__ float4 bcp4[8];                     // bc permuted, x32
    __shared__ unsigned int stage[PCW * 16 * NSTRW];  // 25.6 KB
    int tid = threadIdx.x;

    for (int idx = tid; idx < 10 * 4 * 32; idx += 128) {
        int l = idx & 31, nt = (idx >> 5) & 3, sg = idx >> 7;
        int t = l & 3, gid = l >> 2;
        int col = nt * 8 + gid;
        const float* Ws = (sg < 8) ? (Wk + sg * F_IN * N_HID)
                                   : ((sg == 8) ? bk : Wr);
        float v0 = Ws[(2*t)   * N_HID + col], v1 = Ws[(2*t+1) * N_HID + col];
        float v2 = Ws[(2*t+8) * N_HID + col], v3 = Ws[(2*t+9) * N_HID + col];
        Bf[idx] = make_uint2(bf2(v0 * MSCALE, v1 * MSCALE),
                             bf2(v2 * MSCALE, v3 * MSCALE));
    }
    if (tid < N_HID) {
        int o = (tid >> 1) + ((tid & 1) << 4);        // pi(tid)
        reinterpret_cast<float*>(bcp4)[tid] = bc[o] * MSCALE;
    }
    if (blockIdx.x == 0) {
        if (tid < N_HID) g_pooled[tid] = 0.f;
        if (tid == 32)   g_done = 0;
    }
    __syncthreads();

    int wid = tid >> 5, lane = tid & 31;
    int tile = blockIdx.x * PCW + wid;
    if (tile >= NTILES) return;
    int nb = tile * 16;
    int t = lane & 3, gr = lane >> 2;
    unsigned int* st = stage + wid * (16 * NSTRW);

    // A fragment: rows {gr, gr+8}, k-cols {2t,2t+1} and {2t+8,2t+9}
    const float2* xr0 = reinterpret_cast<const float2*>(x) + (nb + gr) * 8;
    const float2* xr1 = reinterpret_cast<const float2*>(x) + (nb + gr + 8) * 8;
    unsigned int a[4];
    { float2 v;
      v = xr0[t];     a[0] = bf2(v.x, v.y);
      v = xr1[t];     a[1] = bf2(v.x, v.y);
      v = xr0[t + 4]; a[2] = bf2(v.x, v.y);
      v = xr1[t + 4]; a[3] = bf2(v.x, v.y);
    }

#pragma unroll
    for (int sg = 0; sg < 9; sg++) {
        float d[4][4];
#pragma unroll
        for (int nt = 0; nt < 4; nt++) {
            d[nt][0] = d[nt][1] = d[nt][2] = d[nt][3] = 0.f;
            uint2 b = Bf[sg * 128 + nt * 32 + lane];
            mma_bf16(d[nt], a, b.x, b.y);
        }
        unsigned int w00 = (cvt2e4(d[2][1], d[0][1]) << 16) | cvt2e4(d[2][0], d[0][0]);
        unsigned int w01 = (cvt2e4(d[3][1], d[1][1]) << 16) | cvt2e4(d[3][0], d[1][0]);
        unsigned int w10 = (cvt2e4(d[2][3], d[0][3]) << 16) | cvt2e4(d[2][2], d[0][2]);
        unsigned int w11 = (cvt2e4(d[3][3], d[1][3]) << 16) | cvt2e4(d[3][2], d[1][2]);
        int base0 = gr * NSTRW + sg * 8 + t;          // node gr
        int base1 = (gr + 8) * NSTRW + sg * 8 + t;    // node gr+8
        st[base0]     = w00;
        st[base0 + 4] = w01;
        st[base1]     = w10;
        st[base1 + 4] = w11;
    }
    // seed group (Wr): fp32 out + bc, permuted cols, 32x scaled (coalesced)
    {
        float d[4][4];
#pragma unroll
        for (int nt = 0; nt < 4; nt++) {
            d[nt][0] = d[nt][1] = d[nt][2] = d[nt][3] = 0.f;
            uint2 b = Bf[9 * 128 + nt * 32 + lane];
            mma_bf16(d[nt], a, b.x, b.y);
        }
        float4 bl = bcp4[t], bh = bcp4[4 + t];
        float4* ag = reinterpret_cast<float4*>(g_agg);
        ag[(nb + gr) * 8 + t]         = make_float4(d[0][0] + bl.x, d[2][0] + bl.y, d[0][1] + bl.z, d[2][1] + bl.w);
        ag[(nb + gr) * 8 + 4 + t]     = make_float4(d[1][0] + bh.x, d[3][0] + bh.y, d[1][1] + bh.z, d[3][1] + bh.w);
        ag[(nb + gr + 8) * 8 + t]     = make_float4(d[0][2] + bl.x, d[2][2] + bl.y, d[0][3] + bl.z, d[2][3] + bl.w);
        ag[(nb + gr + 8) * 8 + 4 + t] = make_float4(d[1][2] + bh.x, d[3][2] + bh.y, d[1][3] + bh.z, d[3][3] + bh.w);
    }

    // stream the staged M tile out coalesced: 16 rows x 384B (24 uint4)
    __syncwarp();
    if (lane < 24) {
#pragma unroll 8
        for (int n = 0; n < 16; n++) {
            uint4 v = *reinterpret_cast<const uint4*>(&st[n * NSTRW + 4 * lane]);
            g_M4[(nb + n) * 24 + lane] = v;
        }
    }
}

// ---------------------------------------------------------------------------
// Per-edge gather + scatter (UNCHANGED). 8 lanes/edge, 2x LDG.128 + 1x LDG.32,
// reduce-scatter butterfly, red.global.add.v4.f32. At LTS throughput cap.
// ---------------------------------------------------------------------------
__device__ __forceinline__ __half2 cvt8(unsigned int v) {
    unsigned int h;
    asm("cvt.rn.f16x2.e4m3x2 %0, %1;" : "=r"(h) : "h"((unsigned short)v));
    return *reinterpret_cast<__half2*>(&h);
}
__device__ __forceinline__ __half2 shx(__half2 v, int m) {
    unsigned int u = *reinterpret_cast<unsigned int*>(&v);
    u = __shfl_xor_sync(0xffffffffu, u, m);
    return *reinterpret_cast<__half2*>(&u);
}

__global__ void __launch_bounds__(256) k_edge(const int* __restrict__ ei,
                                              const float* __restrict__ e) {
    int gtid = blockIdx.x * 256 + threadIdx.x;
    int edge = gtid >> 3;
    if (edge >= N_EDGES) return;
    int g    = threadIdx.x & 7;
    int hidx = g >> 1;
    bool oddh = hidx & 1;
    bool odd2 = (hidx & 2) != 0;

    int2 pe = reinterpret_cast<const int2*>(ei)[edge];
    int src = pe.x, tgt = pe.y;

    __half2 eA = __float2half2_rn(e[edge * EDGE_S + hidx]);
    __half2 eB = __float2half2_rn(e[edge * EDGE_S + 4 + hidx]);

    const uint4* nb = g_M4 + src * 24;
    uint4 q0 = nb[g];
    uint4 q1 = nb[8 + g];

    __half2 r0 = __hmul2(eA, cvt8(q0.x)), r1 = __hmul2(eA, cvt8(q0.x >> 16));
    __half2 r2 = __hmul2(eA, cvt8(q0.y)), r3 = __hmul2(eA, cvt8(q0.y >> 16));
    __half2 r4 = __hmul2(eA, cvt8(q0.z)), r5 = __hmul2(eA, cvt8(q0.z >> 16));
    __half2 r6 = __hmul2(eA, cvt8(q0.w)), r7 = __hmul2(eA, cvt8(q0.w >> 16));
    r0 = __hfma2(eB, cvt8(q1.x), r0); r1 = __hfma2(eB, cvt8(q1.x >> 16), r1);
    r2 = __hfma2(eB, cvt8(q1.y), r2); r3 = __hfma2(eB, cvt8(q1.y >> 16), r3);
    r4 = __hfma2(eB, cvt8(q1.z), r4); r5 = __hfma2(eB, cvt8(q1.z >> 16), r5);
    r6 = __hfma2(eB, cvt8(q1.w), r6); r7 = __hfma2(eB, cvt8(q1.w >> 16), r7);

    __half2 k0 = __hadd2(oddh ? r2 : r0, shx(oddh ? r0 : r2, 2));
    __half2 k1 = __hadd2(oddh ? r3 : r1, shx(oddh ? r1 : r3, 2));
    __half2 k2 = __hadd2(oddh ? r6 : r4, shx(oddh ? r4 : r6, 2));
    __half2 k3 = __hadd2(oddh ? r7 : r5, shx(oddh ? r5 : r7, 2));
    __half2 c0 = __hadd2(odd2 ? k2 : k0, shx(odd2 ? k0 : k2, 4));
    __half2 c1 = __hadd2(odd2 ? k3 : k1, shx(odd2 ? k1 : k3, 4));

    int ochunk = 16 * (g & 1) + 4 * hidx;
    unsigned int m8 = *reinterpret_cast<const unsigned int*>(
        reinterpret_cast<const char*>(nb) + 256 + ochunk);
    c0 = __hadd2(c0, cvt8(m8));
    c1 = __hadd2(c1, cvt8(m8 >> 16));

    float2 f0 = __half22float2(c0);
    float2 f1 = __half22float2(c1);

    float* dst = &g_agg[tgt * N_HID + ochunk];
    asm volatile("red.global.add.v4.f32 [%0], {%1, %2, %3, %4};"
                 :: "l"(dst), "f"(f0.x), "f"(f0.y), "f"(f1.x), "f"(f1.y) : "memory");
}

// ---------------------------------------------------------------------------
// h = BN(relu(agg/32)); pool; last block: out = pooled@Wd + bd.
// float4 path: warp = 4 nodes/iter (LDG.128), xor-shuffle pool reduce.
// ---------------------------------------------------------------------------
__global__ void __launch_bounds__(256) k_node(const float* __restrict__ gamma,
                                              const float* __restrict__ beta,
                                              const float* __restrict__ mm,
                                              const float* __restrict__ mv,
                                              const float* __restrict__ Wd,
                                              const float* __restrict__ bd,
                                              float* __restrict__ out) {
    __shared__ float4 scl4[8], shf4[8];
    __shared__ float blk[N_HID];
    __shared__ int last;
    int tid = threadIdx.x;
    if (tid < N_HID) {
        blk[tid] = 0.f;
        int o = (tid >> 1) + ((tid & 1) << 4);        // pi(tid)
        float rs = rsqrtf(mv[o] + BN_EPS) * gamma[o];
        reinterpret_cast<float*>(scl4)[tid] = rs * MINV;
        reinterpret_cast<float*>(shf4)[tid] = beta[o] - mm[o] * rs;
    }
    __syncthreads();

    int lane = tid & 31, w = tid >> 5;
    int q = lane & 7, nsub = lane >> 3;
    float4 sc = scl4[q], sh = shf4[q];
    float4 pool = make_float4(0.f, 0.f, 0.f, 0.f);

    const float4* ag4 = reinterpret_cast<const float4*>(g_agg);
    for (int base = blockIdx.x * 32; base < N_NODES; base += gridDim.x * 32) {
        int node = base + w * 4 + nsub;
        if (node < N_NODES) {
            float4 v = ag4[node * 8 + q];
            pool.x += fmaxf(v.x, 0.f) * sc.x + sh.x;
            pool.y += fmaxf(v.y, 0.f) * sc.y + sh.y;
            pool.z += fmaxf(v.z, 0.f) * sc.z + sh.z;
            pool.w += fmaxf(v.w, 0.f) * sc.w + sh.w;
        }
    }
#pragma unroll
    for (int m = 8; m <= 16; m <<= 1) {
        pool.x += __shfl_xor_sync(0xffffffffu, pool.x, m);
        pool.y += __shfl_xor_sync(0xffffffffu, pool.y, m);
        pool.z += __shfl_xor_sync(0xffffffffu, pool.z, m);
        pool.w += __shfl_xor_sync(0xffffffffu, pool.w, m);
    }
    if (lane < 8) {
        atomicAdd(&blk[4 * lane + 0], pool.x);
        atomicAdd(&blk[4 * lane + 1], pool.y);
        atomicAdd(&blk[4 * lane + 2], pool.z);
        atomicAdd(&blk[4 * lane + 3], pool.w);
    }
    __syncthreads();
    if (tid < N_HID) atomicAdd(&g_pooled[tid], blk[tid]);
    __threadfence();
    if (tid == 0)
        last = (atomicAdd(&g_done, 1u) == gridDim.x - 1) ? 1 : 0;
    __syncthreads();
    if (last) {
        if (tid < N_HID) blk[tid] = atomicAdd(&g_pooled[tid], 0.f);
        __syncthreads();
        if (tid < 3) {
            float acc = bd[tid];
#pragma unroll
            for (int j = 0; j < N_HID; j++) {
                int oj = (j >> 1) + ((j & 1) << 4);
                acc += blk[j] * Wd[oj * 3 + tid];
            }
            out[tid] = acc;
        }
    }
}

// ---------------------------------------------------------------------------
extern "C" void kernel_launch(void* const* d_in, const int* in_sizes, int n_in,
                              void* d_out, int out_size) {
    const float* x   = (const float*)d_in[0];
    const int*   ei  = (const int*)  d_in[1];
    const float* e   = (const float*)d_in[2];
    const float* Wk  = (const float*)d_in[3];
    const float* bk  = (const float*)d_in[4];
    const float* Wr  = (const float*)d_in[5];
    const float* bc  = (const float*)d_in[6];
    const float* ga  = (const float*)d_in[7];
    const float* be  = (const float*)d_in[8];
    const float* mm  = (const float*)d_in[9];
    const float* mv  = (const float*)d_in[10];
    const float* Wd  = (const float*)d_in[11];
    const float* bd  = (const float*)d_in[12];
    float* out = (float*)d_out;

    k_precompute<<<(NTILES + PCW - 1) / PCW, 128>>>(x, Wk, bk, Wr, bc);
    k_edge<<<(N_EDGES * 8 + 255) / 256, 256>>>(ei, e);
    k_node<<<592, 256>>>(ga, be, mm, mv, Wd, bd, out);
}

// round 14
// speedup vs baseline: 1.0378x; 1.0360x over previous
#include <cuda_runtime.h>
#include <cuda_fp16.h>
#include <cuda_bf16.h>

#define N_NODES 50000
#define F_IN    16
#define N_HID   32
#define N_EDGES 1000000
#define EDGE_S  8
#define SROWS   9
#define BN_EPS  1e-3f
#define MSCALE  32.0f
#define MINV    0.03125f
#define NTILES  (N_NODES / 16)     // 3125 exactly
// M layout per node: 384 B (3 aligned 128B lines), bytes PERMUTED in o:
//   byte j of s-row (32B at s*32) holds channel o = pi(j) = (j>>1) + (j&1)*16.
// M stores 32*M; g_agg2 (fp16) carries 32x values (perm cols); k_node folds /32.

__device__ uint4 g_M4[N_NODES * 24];        // 19.2 MB fp8 table
__device__ uint2 g_agg2[N_NODES * 8];       // 3.2 MB fp16 agg, perm cols, 32x
__device__ float g_pooled[N_HID];           // permuted order
__device__ unsigned int g_done;
__device__ uint2  g_Bf[10 * 4 * 32];        // prebuilt B fragments (bf16, x32)
__device__ float4 g_bcp4[8];                // bc permuted, x32

__device__ __forceinline__ void mma_bf16(float d[4], const unsigned int a[4],
                                         unsigned int b0, unsigned int b1) {
    asm volatile(
        "mma.sync.aligned.m16n8k16.row.col.f32.bf16.bf16.f32 "
        "{%0,%1,%2,%3}, {%4,%5,%6,%7}, {%8,%9}, {%0,%1,%2,%3};"
        : "+f"(d[0]), "+f"(d[1]), "+f"(d[2]), "+f"(d[3])
        : "r"(a[0]), "r"(a[1]), "r"(a[2]), "r"(a[3]), "r"(b0), "r"(b1));
}
__device__ __forceinline__ unsigned int cvt2e4(float hi, float lo) {
    unsigned short p;
    asm("cvt.rn.satfinite.e4m3x2.f32 %0, %1, %2;" : "=h"(p) : "f"(hi), "f"(lo));
    return (unsigned int)p;
}
__device__ __forceinline__ unsigned int bf2(float lo, float hi) {
    __nv_bfloat162 h = __floats2bfloat162_rn(lo, hi);
    return *reinterpret_cast<unsigned int*>(&h);
}
__device__ __forceinline__ unsigned int h2u(float lo, float hi) {
    __half2 h = __floats2half2_rn(lo, hi);
    return *reinterpret_cast<unsigned int*>(&h);
}

// ---------------------------------------------------------------------------
// One-time (per replay) fragment-table build + accumulator resets.
// ---------------------------------------------------------------------------
__global__ void k_binit(const float* __restrict__ Wk, const float* __restrict__ bk,
                        const float* __restrict__ Wr, const float* __restrict__ bc) {
    int idx = blockIdx.x * 256 + threadIdx.x;
    if (idx < 10 * 4 * 32) {
        int l = idx & 31, nt = (idx >> 5) & 3, sg = idx >> 7;
        int t = l & 3, gid = l >> 2;
        int col = nt * 8 + gid;
        const float* Ws = (sg < 8) ? (Wk + sg * F_IN * N_HID)
                                   : ((sg == 8) ? bk : Wr);
        float v0 = Ws[(2*t)   * N_HID + col], v1 = Ws[(2*t+1) * N_HID + col];
        float v2 = Ws[(2*t+8) * N_HID + col], v3 = Ws[(2*t+9) * N_HID + col];
        g_Bf[idx] = make_uint2(bf2(v0 * MSCALE, v1 * MSCALE),
                               bf2(v2 * MSCALE, v3 * MSCALE));
    }
    if (idx < N_HID) {
        int o = (idx >> 1) + ((idx & 1) << 4);        // pi(idx)
        reinterpret_cast<float*>(g_bcp4)[idx] = bc[o] * MSCALE;
        g_pooled[idx] = 0.f;
    }
    if (idx == 40) g_done = 0;
}

// ---------------------------------------------------------------------------
// Tensor-core precompute: no smem, no syncthreads. Warp = one 16-node tile;
// fragments read from the L1/L2-hot g_Bf table. M table layout unchanged.
// ---------------------------------------------------------------------------
__global__ void __launch_bounds__(256) k_precompute(const float* __restrict__ x) {
    int tid = threadIdx.x;
    int wid = tid >> 5, lane = tid & 31;
    int tile = blockIdx.x * 8 + wid;
    if (tile >= NTILES) return;
    int nb = tile * 16;
    int t = lane & 3, gr = lane >> 2;

    // A fragment: rows {gr, gr+8}, k-cols {2t,2t+1} and {2t+8,2t+9}
    const float2* xr0 = reinterpret_cast<const float2*>(x) + (nb + gr) * 8;
    const float2* xr1 = reinterpret_cast<const float2*>(x) + (nb + gr + 8) * 8;
    unsigned int a[4];
    { float2 v;
      v = xr0[t];     a[0] = bf2(v.x, v.y);
      v = xr1[t];     a[1] = bf2(v.x, v.y);
      v = xr0[t + 4]; a[2] = bf2(v.x, v.y);
      v = xr1[t + 4]; a[3] = bf2(v.x, v.y);
    }

    char* mbase = reinterpret_cast<char*>(g_M4);
#pragma unroll
    for (int sg = 0; sg < 9; sg++) {
        float d[4][4];
#pragma unroll
        for (int nt = 0; nt < 4; nt++) {
            d[nt][0] = d[nt][1] = d[nt][2] = d[nt][3] = 0.f;
            uint2 b = __ldg(&g_Bf[sg * 128 + nt * 32 + lane]);
            mma_bf16(d[nt], a, b.x, b.y);
        }
        unsigned int w00 = (cvt2e4(d[2][1], d[0][1]) << 16) | cvt2e4(d[2][0], d[0][0]);
        unsigned int w01 = (cvt2e4(d[3][1], d[1][1]) << 16) | cvt2e4(d[3][0], d[1][0]);
        unsigned int w10 = (cvt2e4(d[2][3], d[0][3]) << 16) | cvt2e4(d[2][2], d[0][2]);
        unsigned int w11 = (cvt2e4(d[3][3], d[1][3]) << 16) | cvt2e4(d[3][2], d[1][2]);
        long off0 = (long)(nb + gr)     * 384 + sg * 32 + 4 * t;
        long off1 = (long)(nb + gr + 8) * 384 + sg * 32 + 4 * t;
        *reinterpret_cast<unsigned int*>(mbase + off0)      = w00;
        *reinterpret_cast<unsigned int*>(mbase + off0 + 16) = w01;
        *reinterpret_cast<unsigned int*>(mbase + off1)      = w10;
        *reinterpret_cast<unsigned int*>(mbase + off1 + 16) = w11;
    }
    // seed group (Wr): fp16 out + bc, permuted cols, 32x scaled
    {
        float d[4][4];
#pragma unroll
        for (int nt = 0; nt < 4; nt++) {
            d[nt][0] = d[nt][1] = d[nt][2] = d[nt][3] = 0.f;
            uint2 b = __ldg(&g_Bf[9 * 128 + nt * 32 + lane]);
            mma_bf16(d[nt], a, b.x, b.y);
        }
        float4 bl = __ldg(&g_bcp4[t]), bh = __ldg(&g_bcp4[4 + t]);
        g_agg2[(nb + gr) * 8 + t] =
            make_uint2(h2u(d[0][0] + bl.x, d[2][0] + bl.y),
                       h2u(d[0][1] + bl.z, d[2][1] + bl.w));
        g_agg2[(nb + gr) * 8 + 4 + t] =
            make_uint2(h2u(d[1][0] + bh.x, d[3][0] + bh.y),
                       h2u(d[1][1] + bh.z, d[3][1] + bh.w));
        g_agg2[(nb + gr + 8) * 8 + t] =
            make_uint2(h2u(d[0][2] + bl.x, d[2][2] + bl.y),
                       h2u(d[0][3] + bl.z, d[2][3] + bl.w));
        g_agg2[(nb + gr + 8) * 8 + 4 + t] =
            make_uint2(h2u(d[1][2] + bh.x, d[3][2] + bh.y),
                       h2u(d[1][3] + bh.z, d[3][3] + bh.w));
    }
}

// ---------------------------------------------------------------------------
// Per-edge gather + scatter. 8 lanes/edge, 2x LDG.128 + 1x LDG.32 gather,
// reduce-scatter butterfly, fp16x2 vector RED (64B/edge instead of 128B).
// ---------------------------------------------------------------------------
__device__ __forceinline__ __half2 cvt8(unsigned int v) {
    unsigned int h;
    asm("cvt.rn.f16x2.e4m3x2 %0, %1;" : "=r"(h) : "h"((unsigned short)v));
    return *reinterpret_cast<__half2*>(&h);
}
__device__ __forceinline__ __half2 shx(__half2 v, int m) {
    unsigned int u = *reinterpret_cast<unsigned int*>(&v);
    u = __shfl_xor_sync(0xffffffffu, u, m);
    return *reinterpret_cast<__half2*>(&u);
}

__global__ void __launch_bounds__(256) k_edge(const int* __restrict__ ei,
                                              const float* __restrict__ e) {
    int gtid = blockIdx.x * 256 + threadIdx.x;
    int edge = gtid >> 3;
    if (edge >= N_EDGES) return;
    int g    = threadIdx.x & 7;
    int hidx = g >> 1;
    bool oddh = hidx & 1;
    bool odd2 = (hidx & 2) != 0;

    int2 pe = reinterpret_cast<const int2*>(ei)[edge];
    int src = pe.x, tgt = pe.y;

    __half2 eA = __float2half2_rn(e[edge * EDGE_S + hidx]);
    __half2 eB = __float2half2_rn(e[edge * EDGE_S + 4 + hidx]);

    const uint4* nb = g_M4 + src * 24;
    uint4 q0 = nb[g];
    uint4 q1 = nb[8 + g];

    __half2 r0 = __hmul2(eA, cvt8(q0.x)), r1 = __hmul2(eA, cvt8(q0.x >> 16));
    __half2 r2 = __hmul2(eA, cvt8(q0.y)), r3 = __hmul2(eA, cvt8(q0.y >> 16));
    __half2 r4 = __hmul2(eA, cvt8(q0.z)), r5 = __hmul2(eA, cvt8(q0.z >> 16));
    __half2 r6 = __hmul2(eA, cvt8(q0.w)), r7 = __hmul2(eA, cvt8(q0.w >> 16));
    r0 = __hfma2(eB, cvt8(q1.x), r0); r1 = __hfma2(eB, cvt8(q1.x >> 16), r1);
    r2 = __hfma2(eB, cvt8(q1.y), r2); r3 = __hfma2(eB, cvt8(q1.y >> 16), r3);
    r4 = __hfma2(eB, cvt8(q1.z), r4); r5 = __hfma2(eB, cvt8(q1.z >> 16), r5);
    r6 = __hfma2(eB, cvt8(q1.w), r6); r7 = __hfma2(eB, cvt8(q1.w >> 16), r7);

    __half2 k0 = __hadd2(oddh ? r2 : r0, shx(oddh ? r0 : r2, 2));
    __half2 k1 = __hadd2(oddh ? r3 : r1, shx(oddh ? r1 : r3, 2));
    __half2 k2 = __hadd2(oddh ? r6 : r4, shx(oddh ? r4 : r6, 2));
    __half2 k3 = __hadd2(oddh ? r7 : r5, shx(oddh ? r5 : r7, 2));
    __half2 c0 = __hadd2(odd2 ? k2 : k0, shx(odd2 ? k0 : k2, 4));
    __half2 c1 = __hadd2(odd2 ? k3 : k1, shx(odd2 ? k1 : k3, 4));

    int ochunk = 16 * (g & 1) + 4 * hidx;
    unsigned int m8 = *reinterpret_cast<const unsigned int*>(
        reinterpret_cast<const char*>(nb) + 256 + ochunk);
    c0 = __hadd2(c0, cvt8(m8));
    c1 = __hadd2(c1, cvt8(m8 >> 16));

    char* dst = reinterpret_cast<char*>(g_agg2) + (long)(tgt * N_HID + ochunk) * 2;
    unsigned int C0 = *reinterpret_cast<unsigned int*>(&c0);
    unsigned int C1 = *reinterpret_cast<unsigned int*>(&c1);
    asm volatile("red.global.add.noftz.v2.f16x2 [%0], {%1, %2};"
                 :: "l"(dst), "r"(C0), "r"(C1) : "memory");
}

// ---------------------------------------------------------------------------
// h = BN(relu(agg/32)); pool; last block: out = pooled@Wd + bd.
// fp16 agg reads (uint2 = 4 channels/lane), xor-shuffle pool reduce.
// ---------------------------------------------------------------------------
__global__ void __launch_bounds__(256) k_node(const float* __restrict__ gamma,
                                              const float* __restrict__ beta,
                                              const float* __restrict__ mm,
                                              const float* __restrict__ mv,
                                              const float* __restrict__ Wd,
                                              const float* __restrict__ bd,
                                              float* __restrict__ out) {
    __shared__ float4 scl4[8], shf4[8];
    __shared__ float blk[N_HID];
    __shared__ int last;
    int tid = threadIdx.x;
    if (tid < N_HID) {
        blk[tid] = 0.f;
        int o = (tid >> 1) + ((tid & 1) << 4);        // pi(tid)
        float rs = rsqrtf(mv[o] + BN_EPS) * gamma[o];
        reinterpret_cast<float*>(scl4)[tid] = rs * MINV;
        reinterpret_cast<float*>(shf4)[tid] = beta[o] - mm[o] * rs;
    }
    __syncthreads();

    int lane = tid & 31, w = tid >> 5;
    int q = lane & 7, nsub = lane >> 3;
    float4 sc = scl4[q], sh = shf4[q];
    float4 pool = make_float4(0.f, 0.f, 0.f, 0.f);

    for (int base = blockIdx.x * 32; base < N_NODES; base += gridDim.x * 32) {
        int node = base + w * 4 + nsub;
        if (node < N_NODES) {
            uint2 v = g_agg2[node * 8 + q];
            float2 p01 = __half22float2(*reinterpret_cast<__half2*>(&v.x));
            float2 p23 = __half22float2(*reinterpret_cast<__half2*>(&v.y));
            pool.x += fmaxf(p01.x, 0.f) * sc.x + sh.x;
            pool.y += fmaxf(p01.y, 0.f) * sc.y + sh.y;
            pool.z += fmaxf(p23.x, 0.f) * sc.z + sh.z;
            pool.w += fmaxf(p23.y, 0.f) * sc.w + sh.w;
        }
    }
#pragma unroll
    for (int m = 8; m <= 16; m <<= 1) {
        pool.x += __shfl_xor_sync(0xffffffffu, pool.x, m);
        pool.y += __shfl_xor_sync(0xffffffffu, pool.y, m);
        pool.z += __shfl_xor_sync(0xffffffffu, pool.z, m);
        pool.w += __shfl_xor_sync(0xffffffffu, pool.w, m);
    }
    if (lane < 8) {
        atomicAdd(&blk[4 * lane + 0], pool.x);
        atomicAdd(&blk[4 * lane + 1], pool.y);
        atomicAdd(&blk[4 * lane + 2], pool.z);
        atomicAdd(&blk[4 * lane + 3], pool.w);
    }
    __syncthreads();
    if (tid < N_HID) atomicAdd(&g_pooled[tid], blk[tid]);
    __threadfence();
    if (tid == 0)
        last = (atomicAdd(&g_done, 1u) == gridDim.x - 1) ? 1 : 0;
    __syncthreads();
    if (last) {
        if (tid < N_HID) blk[tid] = atomicAdd(&g_pooled[tid], 0.f);
        __syncthreads();
        if (tid < 3) {
            float acc = bd[tid];
#pragma unroll
            for (int j = 0; j < N_HID; j++) {
                int oj = (j >> 1) + ((j & 1) << 4);
                acc += blk[j] * Wd[oj * 3 + tid];
            }
            out[tid] = acc;
        }
    }
}

// ---------------------------------------------------------------------------
extern "C" void kernel_launch(void* const* d_in, const int* in_sizes, int n_in,
                              void* d_out, int out_size) {
    const float* x   = (const float*)d_in[0];
    const int*   ei  = (const int*)  d_in[1];
    const float* e   = (const float*)d_in[2];
    const float* Wk  = (const float*)d_in[3];
    const float* bk  = (const float*)d_in[4];
    const float* Wr  = (const float*)d_in[5];
    const float* bc  = (const float*)d_in[6];
    const float* ga  = (const float*)d_in[7];
    const float* be  = (const float*)d_in[8];
    const float* mm  = (const float*)d_in[9];
    const float* mv  = (const float*)d_in[10];
    const float* Wd  = (const float*)d_in[11];
    const float* bd  = (const float*)d_in[12];
    float* out = (float*)d_out;

    k_binit<<<5, 256>>>(Wk, bk, Wr, bc);
    k_precompute<<<(NTILES + 7) / 8, 256>>>(x);
    k_edge<<<(N_EDGES * 8 + 255) / 256, 256>>>(ei, e);
    k_node<<<592, 256>>>(ga, be, mm, mv, Wd, bd, out);
}

// round 15
// speedup vs baseline: 1.0384x; 1.0006x over previous
#include <cuda_runtime.h>
#include <cuda_fp16.h>
#include <cuda_bf16.h>

#define N_NODES 50000
#define F_IN    16
#define N_HID   32
#define N_EDGES 1000000
#define EDGE_S  8
#define SROWS   9
#define BN_EPS  1e-3f
#define MSCALE  32.0f
#define MINV    0.03125f
#define NTILES  (N_NODES / 16)     // 3125 exactly
// M layout per node: 384 B (3 aligned 128B lines), bytes PERMUTED in o:
//   byte j of s-row (32B at s*32) holds channel o = pi(j) = (j>>1) + (j&1)*16.
// M stores 32*M; g_agg2 (fp16) carries 32x values (perm cols); k_node folds /32.

__device__ uint4 g_M4[N_NODES * 24];        // 19.2 MB fp8 table
__device__ uint2 g_agg2[N_NODES * 8];       // 3.2 MB fp16 agg, perm cols, 32x
__device__ float g_pooled[N_HID];           // permuted order
__device__ unsigned int g_done;
__device__ uint2  g_Bf[10 * 4 * 32];        // prebuilt B fragments (bf16, x32)
__device__ float4 g_bcp4[8];                // bc permuted, x32

__device__ __forceinline__ void mma_bf16(float d[4], const unsigned int a[4],
                                         unsigned int b0, unsigned int b1) {
    asm volatile(
        "mma.sync.aligned.m16n8k16.row.col.f32.bf16.bf16.f32 "
        "{%0,%1,%2,%3}, {%4,%5,%6,%7}, {%8,%9}, {%0,%1,%2,%3};"
        : "+f"(d[0]), "+f"(d[1]), "+f"(d[2]), "+f"(d[3])
        : "r"(a[0]), "r"(a[1]), "r"(a[2]), "r"(a[3]), "r"(b0), "r"(b1));
}
__device__ __forceinline__ unsigned int cvt2e4(float hi, float lo) {
    unsigned short p;
    asm("cvt.rn.satfinite.e4m3x2.f32 %0, %1, %2;" : "=h"(p) : "f"(hi), "f"(lo));
    return (unsigned int)p;
}
__device__ __forceinline__ unsigned int bf2(float lo, float hi) {
    __nv_bfloat162 h = __floats2bfloat162_rn(lo, hi);
    return *reinterpret_cast<unsigned int*>(&h);
}
__device__ __forceinline__ unsigned int h2u(float lo, float hi) {
    __half2 h = __floats2half2_rn(lo, hi);
    return *reinterpret_cast<unsigned int*>(&h);
}

// ---------------------------------------------------------------------------
// One-time (per replay) fragment-table build + accumulator resets.
// ---------------------------------------------------------------------------
__global__ void k_binit(const float* __restrict__ Wk, const float* __restrict__ bk,
                        const float* __restrict__ Wr, const float* __restrict__ bc) {
    int idx = blockIdx.x * 256 + threadIdx.x;
    if (idx < 10 * 4 * 32) {
        int l = idx & 31, nt = (idx >> 5) & 3, sg = idx >> 7;
        int t = l & 3, gid = l >> 2;
        int col = nt * 8 + gid;
        const float* Ws = (sg < 8) ? (Wk + sg * F_IN * N_HID)
                                   : ((sg == 8) ? bk : Wr);
        float v0 = Ws[(2*t)   * N_HID + col], v1 = Ws[(2*t+1) * N_HID + col];
        float v2 = Ws[(2*t+8) * N_HID + col], v3 = Ws[(2*t+9) * N_HID + col];
        g_Bf[idx] = make_uint2(bf2(v0 * MSCALE, v1 * MSCALE),
                               bf2(v2 * MSCALE, v3 * MSCALE));
    }
    if (idx < N_HID) {
        int o = (idx >> 1) + ((idx & 1) << 4);        // pi(idx)
        reinterpret_cast<float*>(g_bcp4)[idx] = bc[o] * MSCALE;
        g_pooled[idx] = 0.f;
    }
    if (idx == 40) g_done = 0;
}

// ---------------------------------------------------------------------------
// Tensor-core precompute: no smem, no syncthreads. Warp = one 16-node tile;
// fragments read from the L1/L2-hot g_Bf table. M table layout unchanged.
// ---------------------------------------------------------------------------
__global__ void __launch_bounds__(256) k_precompute(const float* __restrict__ x) {
    int tid = threadIdx.x;
    int wid = tid >> 5, lane = tid & 31;
    int tile = blockIdx.x * 8 + wid;
    if (tile >= NTILES) return;
    int nb = tile * 16;
    int t = lane & 3, gr = lane >> 2;

    // A fragment: rows {gr, gr+8}, k-cols {2t,2t+1} and {2t+8,2t+9}
    const float2* xr0 = reinterpret_cast<const float2*>(x) + (nb + gr) * 8;
    const float2* xr1 = reinterpret_cast<const float2*>(x) + (nb + gr + 8) * 8;
    unsigned int a[4];
    { float2 v;
      v = xr0[t];     a[0] = bf2(v.x, v.y);
      v = xr1[t];     a[1] = bf2(v.x, v.y);
      v = xr0[t + 4]; a[2] = bf2(v.x, v.y);
      v = xr1[t + 4]; a[3] = bf2(v.x, v.y);
    }

    char* mbase = reinterpret_cast<char*>(g_M4);
#pragma unroll
    for (int sg = 0; sg < 9; sg++) {
        float d[4][4];
#pragma unroll
        for (int nt = 0; nt < 4; nt++) {
            d[nt][0] = d[nt][1] = d[nt][2] = d[nt][3] = 0.f;
            uint2 b = __ldg(&g_Bf[sg * 128 + nt * 32 + lane]);
            mma_bf16(d[nt], a, b.x, b.y);
        }
        unsigned int w00 = (cvt2e4(d[2][1], d[0][1]) << 16) | cvt2e4(d[2][0], d[0][0]);
        unsigned int w01 = (cvt2e4(d[3][1], d[1][1]) << 16) | cvt2e4(d[3][0], d[1][0]);
        unsigned int w10 = (cvt2e4(d[2][3], d[0][3]) << 16) | cvt2e4(d[2][2], d[0][2]);
        unsigned int w11 = (cvt2e4(d[3][3], d[1][3]) << 16) | cvt2e4(d[3][2], d[1][2]);
        long off0 = (long)(nb + gr)     * 384 + sg * 32 + 4 * t;
        long off1 = (long)(nb + gr + 8) * 384 + sg * 32 + 4 * t;
        *reinterpret_cast<unsigned int*>(mbase + off0)      = w00;
        *reinterpret_cast<unsigned int*>(mbase + off0 + 16) = w01;
        *reinterpret_cast<unsigned int*>(mbase + off1)      = w10;
        *reinterpret_cast<unsigned int*>(mbase + off1 + 16) = w11;
    }
    // seed group (Wr): fp16 out + bc, permuted cols, 32x scaled
    {
        float d[4][4];
#pragma unroll
        for (int nt = 0; nt < 4; nt++) {
            d[nt][0] = d[nt][1] = d[nt][2] = d[nt][3] = 0.f;
            uint2 b = __ldg(&g_Bf[9 * 128 + nt * 32 + lane]);
            mma_bf16(d[nt], a, b.x, b.y);
        }
        float4 bl = __ldg(&g_bcp4[t]), bh = __ldg(&g_bcp4[4 + t]);
        g_agg2[(nb + gr) * 8 + t] =
            make_uint2(h2u(d[0][0] + bl.x, d[2][0] + bl.y),
                       h2u(d[0][1] + bl.z, d[2][1] + bl.w));
        g_agg2[(nb + gr) * 8 + 4 + t] =
            make_uint2(h2u(d[1][0] + bh.x, d[3][0] + bh.y),
                       h2u(d[1][1] + bh.z, d[3][1] + bh.w));
        g_agg2[(nb + gr + 8) * 8 + t] =
            make_uint2(h2u(d[0][2] + bl.x, d[2][2] + bl.y),
                       h2u(d[0][3] + bl.z, d[2][3] + bl.w));
        g_agg2[(nb + gr + 8) * 8 + 4 + t] =
            make_uint2(h2u(d[1][2] + bh.x, d[3][2] + bh.y),
                       h2u(d[1][3] + bh.z, d[3][3] + bh.w));
    }
}

// ---------------------------------------------------------------------------
// Per-edge gather + scatter. 8 lanes/edge, 2x LDG.128 + 1x LDG.32 gather,
// reduce-scatter butterfly, fp16x2 vector RED (64B/edge instead of 128B).
// ---------------------------------------------------------------------------
__device__ __forceinline__ __half2 cvt8(unsigned int v) {
    unsigned int h;
    asm("cvt.rn.f16x2.e4m3x2 %0, %1;" : "=r"(h) : "h"((unsigned short)v));
    return *reinterpret_cast<__half2*>(&h);
}
__device__ __forceinline__ __half2 shx(__half2 v, int m) {
    unsigned int u = *reinterpret_cast<unsigned int*>(&v);
    u = __shfl_xor_sync(0xffffffffu, u, m);
    return *reinterpret_cast<__half2*>(&u);
}

__global__ void __launch_bounds__(256) k_edge(const int* __restrict__ ei,
                                              const float* __restrict__ e) {
    int gtid = blockIdx.x * 256 + threadIdx.x;
    int edge = gtid >> 3;
    if (edge >= N_EDGES) return;
    int g    = threadIdx.x & 7;
    int hidx = g >> 1;
    bool oddh = hidx & 1;
    bool odd2 = (hidx & 2) != 0;

    int2 pe = reinterpret_cast<const int2*>(ei)[edge];
    int src = pe.x, tgt = pe.y;

    __half2 eA = __float2half2_rn(e[edge * EDGE_S + hidx]);
    __half2 eB = __float2half2_rn(e[edge * EDGE_S + 4 + hidx]);

    const uint4* nb = g_M4 + src * 24;
    uint4 q0 = nb[g];
    uint4 q1 = nb[8 + g];

    __half2 r0 = __hmul2(eA, cvt8(q0.x)), r1 = __hmul2(eA, cvt8(q0.x >> 16));
    __half2 r2 = __hmul2(eA, cvt8(q0.y)), r3 = __hmul2(eA, cvt8(q0.y >> 16));
    __half2 r4 = __hmul2(eA, cvt8(q0.z)), r5 = __hmul2(eA, cvt8(q0.z >> 16));
    __half2 r6 = __hmul2(eA, cvt8(q0.w)), r7 = __hmul2(eA, cvt8(q0.w >> 16));
    r0 = __hfma2(eB, cvt8(q1.x), r0); r1 = __hfma2(eB, cvt8(q1.x >> 16), r1);
    r2 = __hfma2(eB, cvt8(q1.y), r2); r3 = __hfma2(eB, cvt8(q1.y >> 16), r3);
    r4 = __hfma2(eB, cvt8(q1.z), r4); r5 = __hfma2(eB, cvt8(q1.z >> 16), r5);
    r6 = __hfma2(eB, cvt8(q1.w), r6); r7 = __hfma2(eB, cvt8(q1.w >> 16), r7);

    __half2 k0 = __hadd2(oddh ? r2 : r0, shx(oddh ? r0 : r2, 2));
    __half2 k1 = __hadd2(oddh ? r3 : r1, shx(oddh ? r1 : r3, 2));
    __half2 k2 = __hadd2(oddh ? r6 : r4, shx(oddh ? r4 : r6, 2));
    __half2 k3 = __hadd2(oddh ? r7 : r5, shx(oddh ? r5 : r7, 2));
    __half2 c0 = __hadd2(odd2 ? k2 : k0, shx(odd2 ? k0 : k2, 4));
    __half2 c1 = __hadd2(odd2 ? k3 : k1, shx(odd2 ? k1 : k3, 4));

    int ochunk = 16 * (g & 1) + 4 * hidx;
    unsigned int m8 = *reinterpret_cast<const unsigned int*>(
        reinterpret_cast<const char*>(nb) + 256 + ochunk);
    c0 = __hadd2(c0, cvt8(m8));
    c1 = __hadd2(c1, cvt8(m8 >> 16));

    char* dst = reinterpret_cast<char*>(g_agg2) + (long)(tgt * N_HID + ochunk) * 2;
    unsigned int C0 = *reinterpret_cast<unsigned int*>(&c0);
    unsigned int C1 = *reinterpret_cast<unsigned int*>(&c1);
    asm volatile("red.global.add.noftz.v2.f16x2 [%0], {%1, %2};"
                 :: "l"(dst), "r"(C0), "r"(C1) : "memory");
}

// ---------------------------------------------------------------------------
// h = BN(relu(agg/32)); pool; last block: out = pooled@Wd + bd.
// fp16 agg reads (uint2 = 4 channels/lane), xor-shuffle pool reduce.
// ---------------------------------------------------------------------------
__global__ void __launch_bounds__(256) k_node(const float* __restrict__ gamma,
                                              const float* __restrict__ beta,
                                              const float* __restrict__ mm,
                                              const float* __restrict__ mv,
                                              const float* __restrict__ Wd,
                                              const float* __restrict__ bd,
                                              float* __restrict__ out) {
    __shared__ float4 scl4[8], shf4[8];
    __shared__ float blk[N_HID];
    __shared__ int last;
    int tid = threadIdx.x;
    if (tid < N_HID) {
        blk[tid] = 0.f;
        int o = (tid >> 1) + ((tid & 1) << 4);        // pi(tid)
        float rs = rsqrtf(mv[o] + BN_EPS) * gamma[o];
        reinterpret_cast<float*>(scl4)[tid] = rs * MINV;
        reinterpret_cast<float*>(shf4)[tid] = beta[o] - mm[o] * rs;
    }
    __syncthreads();

    int lane = tid & 31, w = tid >> 5;
    int q = lane & 7, nsub = lane >> 3;
    float4 sc = scl4[q], sh = shf4[q];
    float4 pool = make_float4(0.f, 0.f, 0.f, 0.f);

    for (int base = blockIdx.x * 32; base < N_NODES; base += gridDim.x * 32) {
        int node = base + w * 4 + nsub;
        if (node < N_NODES) {
            uint2 v = g_agg2[node * 8 + q];
            float2 p01 = __half22float2(*reinterpret_cast<__half2*>(&v.x));
            float2 p23 = __half22float2(*reinterpret_cast<__half2*>(&v.y));
            pool.x += fmaxf(p01.x, 0.f) * sc.x + sh.x;
            pool.y += fmaxf(p01.y, 0.f) * sc.y + sh.y;
            pool.z += fmaxf(p23.x, 0.f) * sc.z + sh.z;
            pool.w += fmaxf(p23.y, 0.f) * sc.w + sh.w;
        }
    }
#pragma unroll
    for (int m = 8; m <= 16; m <<= 1) {
        pool.x += __shfl_xor_sync(0xffffffffu, pool.x, m);
        pool.y += __shfl_xor_sync(0xffffffffu, pool.y, m);
        pool.z += __shfl_xor_sync(0xffffffffu, pool.z, m);
        pool.w += __shfl_xor_sync(0xffffffffu, pool.w, m);
    }
    if (lane < 8) {
        atomicAdd(&blk[4 * lane + 0], pool.x);
        atomicAdd(&blk[4 * lane + 1], pool.y);
        atomicAdd(&blk[4 * lane + 2], pool.z);
        atomicAdd(&blk[4 * lane + 3], pool.w);
    }
    __syncthreads();
    if (tid < N_HID) atomicAdd(&g_pooled[tid], blk[tid]);
    __threadfence();
    if (tid == 0)
        last = (atomicAdd(&g_done, 1u) == gridDim.x - 1) ? 1 : 0;
    __syncthreads();
    if (last) {
        if (tid < N_HID) blk[tid] = atomicAdd(&g_pooled[tid], 0.f);
        __syncthreads();
        if (tid < 3) {
            float acc = bd[tid];
#pragma unroll
            for (int j = 0; j < N_HID; j++) {
                int oj = (j >> 1) + ((j & 1) << 4);
                acc += blk[j] * Wd[oj * 3 + tid];
            }
            out[tid] = acc;
        }
    }
}

// ---------------------------------------------------------------------------
extern "C" void kernel_launch(void* const* d_in, const int* in_sizes, int n_in,
                              void* d_out, int out_size) {
    const float* x   = (const float*)d_in[0];
    const int*   ei  = (const int*)  d_in[1];
    const float* e   = (const float*)d_in[2];
    const float* Wk  = (const float*)d_in[3];
    const float* bk  = (const float*)d_in[4];
    const float* Wr  = (const float*)d_in[5];
    const float* bc  = (const float*)d_in[6];
    const float* ga  = (const float*)d_in[7];
    const float* be  = (const float*)d_in[8];
    const float* mm  = (const float*)d_in[9];
    const float* mv  = (const float*)d_in[10];
    const float* Wd  = (const float*)d_in[11];
    const float* bd  = (const float*)d_in[12];
    float* out = (float*)d_out;

    k_binit<<<5, 256>>>(Wk, bk, Wr, bc);
    k_precompute<<<(NTILES + 7) / 8, 256>>>(x);
    k_edge<<<(N_EDGES * 8 + 255) / 256, 256>>>(ei, e);
    k_node<<<592, 256>>>(ga, be, mm, mv, Wd, bd, out);
}